// round 15
// baseline (speedup 1.0000x reference)
#include <cuda_runtime.h>
#include <cuda_bf16.h>
#include <cstdint>
#include <cstddef>

// ---------------------------------------------------------------------------
// LSTM: B=512, T=512, I=128, H=512, O=128. Gates [g,i,f,o].
// Persistent 128 CTAs x 256 threads. Each CTA owns TWO independent tiles
// (same q = 16 h-cols x 4 gates, two different 64-row batch groups A/B).
// While tile A's h exchange is in flight, tile B computes (and vice versa),
// hiding the inter-CTA latency chain that pinned rounds 11-14 at ~6.6us/step.
// ---------------------------------------------------------------------------

#define NCTA 128

__device__ __nv_bfloat16  g_wxtb[2048 * 128];            // Wx^T [n][k] bf16
__device__ __nv_bfloat16  g_wht[2048 * 512];             // Wh^T [n][k] bf16
__device__ __nv_bfloat16  g_xb[(size_t)512 * 512 * 128]; // x bf16 [b][t][i]
__device__ __nv_bfloat16  g_h[2][512 * 512];             // ping-pong h
__device__ float          g_hfinal[512 * 512];           // final h fp32
__device__ unsigned       g_barr[8 * 32];                // per-group ctr @ [g*32]

// ---------------- PTX helpers ----------------------------------------------
__device__ __forceinline__ unsigned smem_u32(const void* p) {
    return (unsigned)__cvta_generic_to_shared(p);
}
__device__ __forceinline__ void cp16(void* dst_smem, const void* src) {
    asm volatile("cp.async.cg.shared.global [%0], [%1], 16;"
                 :: "r"(smem_u32(dst_smem)), "l"(src) : "memory");
}
__device__ __forceinline__ void cp_commit() {
    asm volatile("cp.async.commit_group;" ::: "memory");
}
template <int N>
__device__ __forceinline__ void cp_wait() {
    asm volatile("cp.async.wait_group %0;" :: "n"(N) : "memory");
}
__device__ __forceinline__ void ldm4(unsigned r[4], unsigned addr) {
    asm volatile("ldmatrix.sync.aligned.m8n8.x4.shared.b16 {%0,%1,%2,%3}, [%4];"
                 : "=r"(r[0]), "=r"(r[1]), "=r"(r[2]), "=r"(r[3]) : "r"(addr));
}
__device__ __forceinline__ void mma_bf16(float& d0, float& d1, float& d2, float& d3,
                                         unsigned a0, unsigned a1, unsigned a2, unsigned a3,
                                         unsigned b0, unsigned b1) {
    asm volatile(
        "mma.sync.aligned.m16n8k16.row.col.f32.bf16.bf16.f32 "
        "{%0,%1,%2,%3},{%4,%5,%6,%7},{%8,%9},{%0,%1,%2,%3};"
        : "+f"(d0), "+f"(d1), "+f"(d2), "+f"(d3)
        : "r"(a0), "r"(a1), "r"(a2), "r"(a3), "r"(b0), "r"(b1));
}
__device__ __forceinline__ float tanhfast(float x) {
    float y;
    asm("tanh.approx.f32 %0, %1;" : "=f"(y) : "f"(x));
    return y;
}
__device__ __forceinline__ float fsig(float x) {
    return fmaf(0.5f, tanhfast(0.5f * x), 0.5f);
}
__device__ __forceinline__ void barpair(int wm) {        // warps {wm, wm+4}
    asm volatile("bar.sync %0, 64;" :: "r"(wm + 1) : "memory");
}

// ---- mma block: M=16 x N=(4 gates x n8), 8 k16 iterations --------------------
// aAddr: A m16 fragment base; bAddr: gates {0,1}; bAddr+gs: gates {2,3}.
__device__ __forceinline__ void mma_block8(unsigned aAddr, unsigned bAddr,
                                           unsigned gs, float acc[4][4]) {
#pragma unroll
    for (int k16 = 0; k16 < 8; k16++) {
        unsigned a[4], b01[4], b23[4];
        ldm4(a, aAddr + k16 * 32);
        ldm4(b01, bAddr + k16 * 32);
        ldm4(b23, bAddr + gs + k16 * 32);
        mma_bf16(acc[0][0], acc[0][1], acc[0][2], acc[0][3],
                 a[0], a[1], a[2], a[3], b01[0], b01[1]);
        mma_bf16(acc[1][0], acc[1][1], acc[1][2], acc[1][3],
                 a[0], a[1], a[2], a[3], b01[2], b01[3]);
        mma_bf16(acc[2][0], acc[2][1], acc[2][2], acc[2][3],
                 a[0], a[1], a[2], a[3], b23[0], b23[1]);
        mma_bf16(acc[3][0], acc[3][1], acc[3][2], acc[3][3],
                 a[0], a[1], a[2], a[3], b23[2], b23[3]);
    }
}

// ---------------- converts ---------------------------------------------------
__global__ void conv_w(const float* __restrict__ Wx, const float* __restrict__ Wh) {
    int tid = blockIdx.x * blockDim.x + threadIdx.x;
    int stride = gridDim.x * blockDim.x;
    for (int o = tid; o < 2048 * 128; o += stride) {
        int k = o & 127, n = o >> 7;
        g_wxtb[o] = __float2bfloat16(Wx[(size_t)k * 2048 + n]);
    }
    for (int o = tid; o < 2048 * 512; o += stride) {
        int k = o & 511, n = o >> 9;
        g_wht[o] = __float2bfloat16(Wh[(size_t)k * 2048 + n]);
    }
}

__global__ void conv_x(const float* __restrict__ x) {
    const float4* x4 = (const float4*)x;
    size_t N4 = (size_t)512 * 512 * 128 / 4;
    for (size_t o = (size_t)blockIdx.x * blockDim.x + threadIdx.x; o < N4;
         o += (size_t)gridDim.x * blockDim.x) {
        float4 v = x4[o];
        __nv_bfloat162 lo = __floats2bfloat162_rn(v.x, v.y);
        __nv_bfloat162 hi = __floats2bfloat162_rn(v.z, v.w);
        uint2 pk;
        pk.x = *(unsigned*)&lo;
        pk.y = *(unsigned*)&hi;
        *(uint2*)(g_xb + o * 4) = pk;
    }
}

__global__ void reset_k() {
    int tid = blockIdx.x * blockDim.x + threadIdx.x;
    if (tid < 8 * 32) g_barr[tid] = 0u;
    for (int o = tid; o < 512 * 512; o += gridDim.x * blockDim.x)
        g_h[0][o] = __float2bfloat16(0.f);
}

// ---------------- persistent recurrence --------------------------------------
// smem (bytes):
//   Whs [64][520] bf16 : 0      .. 66560
//   Wxs [64][136] bf16 : 66560  .. 83968
//   HA0 [64][136]      : 83968  .. 101376
//   HA1 [64][136]      : 101376 .. 118784
//   HB0 [64][136]      : 118784 .. 136192
//   HB1 [64][136]      : 136192 .. 153600
//   xsA [64][136]      : 153600 .. 171008
//   xsB [64][136]      : 171008 .. 188416
#define OFF_WX  66560
#define OFF_HA0 83968
#define OFF_HA1 101376
#define OFF_HB0 118784
#define OFF_HB1 136192
#define OFF_XA  153600
#define OFF_XB  171008
#define REC_SMEM 188416

// one tile's full time step (poll -> stage -> x-mma -> 4 h-chunks -> gates)
__device__ __forceinline__ void tile_step(
    int t, int rbase, char* smem,
    int oH0, int oH1, int oX,                 // staging byte offsets
    unsigned sH0, unsigned sH1, unsigned sX,  // per-thread A-frag ldm addrs
    unsigned sWhB, unsigned sWxB,
    volatile unsigned* ctr,
    const float bz[4][2], float c[4],
    int lane, int wm, int wn, int srow, int tr, int tc, int q)
{
    const unsigned GS_WH = 32u * 1040u;
    const unsigned GS_WX = 32u * 272u;

    // poll: all h(t) writers of this group arrived (t=0 trivially passes)
    {
        unsigned tgt = (unsigned)t * 256u;
        while (*ctr < tgt) { }
        __threadfence();
    }
    const __nv_bfloat16* hsrc = g_h[t & 1] + (size_t)rbase * 512;

    // stage chunk0 -> H0, chunk1 -> H1 (this warp's 8 rows)
#pragma unroll
    for (int i = lane; i < 128; i += 32) {
        int r = srow + (i >> 4), ch = i & 15;
        cp16(smem + oH0 + r * 272 + ch * 16, hsrc + (size_t)r * 512 + 0 * 128 + ch * 8);
    }
    cp_commit();
#pragma unroll
    for (int i = lane; i < 128; i += 32) {
        int r = srow + (i >> 4), ch = i & 15;
        cp16(smem + oH1 + r * 272 + ch * 16, hsrc + (size_t)r * 512 + 1 * 128 + ch * 8);
    }
    cp_commit();   // pending {h0,h1} (+ possibly drained older groups)

    // x-GEMM (xs staged during this tile's previous step; drained since)
    float acc[4][4];
#pragma unroll
    for (int g = 0; g < 4; g++) {
        acc[g][0] = bz[g][0]; acc[g][1] = bz[g][1];
        acc[g][2] = bz[g][0]; acc[g][3] = bz[g][1];
    }
    mma_block8(sX, sWxB, GS_WX, acc);

    // kc=0
    cp_wait<1>(); barpair(wm);
    mma_block8(sH0, sWhB, GS_WH, acc);
    // stage chunk2 -> H0
#pragma unroll
    for (int i = lane; i < 128; i += 32) {
        int r = srow + (i >> 4), ch = i & 15;
        cp16(smem + oH0 + r * 272 + ch * 16, hsrc + (size_t)r * 512 + 2 * 128 + ch * 8);
    }
    cp_commit();   // {h1,h2}
    // kc=1
    cp_wait<1>(); barpair(wm);
    mma_block8(sH1, sWhB + 256, GS_WH, acc);
    // stage chunk3 -> H1, and xs(t+1)
#pragma unroll
    for (int i = lane; i < 128; i += 32) {
        int r = srow + (i >> 4), ch = i & 15;
        cp16(smem + oH1 + r * 272 + ch * 16, hsrc + (size_t)r * 512 + 3 * 128 + ch * 8);
    }
    cp_commit();   // {h2,h3}
    if (t < 511) {
#pragma unroll
        for (int i = lane; i < 128; i += 32) {
            int r = srow + (i >> 4), ch = i & 15;
            cp16(smem + oX + r * 272 + ch * 16,
                 g_xb + ((size_t)(rbase + r) * 512 + (t + 1)) * 128 + ch * 8);
        }
        cp_commit();   // {h2,h3,x'}
        cp_wait<2>();
    } else {
        cp_wait<1>();
    }
    barpair(wm);
    mma_block8(sH0, sWhB + 512, GS_WH, acc);    // kc=2
    if (t < 511) cp_wait<1>(); else cp_wait<0>();
    barpair(wm);
    mma_block8(sH1, sWhB + 768, GS_WH, acc);    // kc=3
    // pending carried out: {x'} if t<511 (drained by the partner tile's waits)

    // ---- gates + state update + h writeback ----
    const int grow = rbase + wm * 16 + tr;
    const int hcol = q * 16 + wn * 8 + tc;
    float hv[4];
#pragma unroll
    for (int e = 0; e < 4; e++) {
        float gv = tanhfast(acc[0][e]);
        float iv = fsig(acc[1][e]);
        float fv = fsig(acc[2][e]);
        float ov = fsig(acc[3][e]);
        float cn = gv * iv + c[e] * fv;
        c[e] = cn;
        hv[e] = tanhfast(cn) * ov;
    }
    if (t < 511) {
        __nv_bfloat16* hd = g_h[(t + 1) & 1];
        *(__nv_bfloat162*)(hd + (size_t)grow * 512 + hcol) =
            __floats2bfloat162_rn(hv[0], hv[1]);
        *(__nv_bfloat162*)(hd + (size_t)(grow + 8) * 512 + hcol) =
            __floats2bfloat162_rn(hv[2], hv[3]);
        __syncwarp();
        if (lane == 0) {
            __threadfence();
            atomicAdd((unsigned*)ctr, 1u);   // 32 CTAs x 8 warps = 256 per step
        }
    } else {
        *(float2*)(g_hfinal + (size_t)grow * 512 + hcol) = make_float2(hv[0], hv[1]);
        *(float2*)(g_hfinal + (size_t)(grow + 8) * 512 + hcol) = make_float2(hv[2], hv[3]);
    }
}

__global__ void __launch_bounds__(256, 1) lstm_rec(const float* __restrict__ bias) {
    extern __shared__ char smem[];
    __nv_bfloat16* Whs = (__nv_bfloat16*)smem;
    __nv_bfloat16* Wxs = (__nv_bfloat16*)(smem + OFF_WX);

    const int tid = threadIdx.x;
    const int lane = tid & 31, warp = tid >> 5;
    const int wm = warp & 3, wn = warp >> 2;
    const int q = blockIdx.x & 31, gpair = blockIdx.x >> 5;
    const int rbaseA = gpair * 128;          // group 2*gpair   (64 rows)
    const int rbaseB = rbaseA + 64;          // group 2*gpair+1 (64 rows)
    const int tr = lane >> 2, tc = (lane & 3) * 2;
    const int srow = wm * 16 + wn * 8;       // this warp's 8-row staging slice
    volatile unsigned* ctrA = (volatile unsigned*)&g_barr[(2 * gpair) << 5];
    volatile unsigned* ctrB = (volatile unsigned*)&g_barr[(2 * gpair + 1) << 5];

    // ---- per-thread ldmatrix addresses (round-10-verified formulas) ----
    const unsigned aoff =
        (unsigned)(wm * 16 + (lane & 7) + ((lane >> 3) & 1) * 8) * 272u +
        (unsigned)((lane >> 4) & 1) * 16u;
    const unsigned bRow =
        (unsigned)(((lane >> 4) & 1) * 16 + wn * 8 + (lane & 7));
    const unsigned bColSel = (unsigned)((lane >> 3) & 1) * 16u;
    const unsigned sWhB = smem_u32(Whs) + bRow * 1040u + bColSel;   // + kc*256
    const unsigned sWxB = smem_u32(Wxs) + bRow * 272u + bColSel;
    const unsigned base = smem_u32(smem);
    const unsigned sHA0 = base + OFF_HA0 + aoff, sHA1 = base + OFF_HA1 + aoff;
    const unsigned sHB0 = base + OFF_HB0 + aoff, sHB1 = base + OFF_HB1 + aoff;
    const unsigned sXA  = base + OFF_XA + aoff,  sXB  = base + OFF_XB + aoff;

    // ---- prologue: Whs, Wxs, xsA(0), xsB(0) ----
    for (int i = tid; i < 4096; i += 256) {          // Whs: 64 rows x 64 ch
        int rowi = i >> 6, ch = i & 63;
        int gate = rowi >> 4, lc = rowi & 15;
        cp16(&Whs[rowi * 520 + ch * 8],
             g_wht + (size_t)(gate * 512 + q * 16 + lc) * 512 + ch * 8);
    }
    for (int i = tid; i < 1024; i += 256) {          // Wxs: 64 rows x 16 ch
        int rowi = i >> 4, ch = i & 15;
        int gate = rowi >> 4, lc = rowi & 15;
        cp16(&Wxs[rowi * 136 + ch * 8],
             g_wxtb + (size_t)(gate * 512 + q * 16 + lc) * 128 + ch * 8);
    }
    for (int i = tid; i < 1024; i += 256) {          // xsA(0)
        int r = i >> 4, ch = i & 15;
        cp16(smem + OFF_XA + r * 272 + ch * 16,
             g_xb + ((size_t)(rbaseA + r) * 512 + 0) * 128 + ch * 8);
    }
    for (int i = tid; i < 1024; i += 256) {          // xsB(0)
        int r = i >> 4, ch = i & 15;
        cp16(smem + OFF_XB + r * 272 + ch * 16,
             g_xb + ((size_t)(rbaseB + r) * 512 + 0) * 128 + ch * 8);
    }
    cp_commit(); cp_wait<0>(); __syncthreads();

    float bz[4][2];
    {
        int col = q * 16 + wn * 8 + tc;
#pragma unroll
        for (int g = 0; g < 4; g++) {
            bz[g][0] = bias[g * 512 + col];
            bz[g][1] = bias[g * 512 + col + 1];
        }
    }
    float cA[4], cB[4];
#pragma unroll
    for (int e = 0; e < 4; e++) { cA[e] = 0.f; cB[e] = 0.f; }

    for (int t = 0; t < 512; ++t) {
        tile_step(t, rbaseA, smem, OFF_HA0, OFF_HA1, OFF_XA,
                  sHA0, sHA1, sXA, sWhB, sWxB, ctrA,
                  bz, cA, lane, wm, wn, srow, tr, tc, q);
        tile_step(t, rbaseB, smem, OFF_HB0, OFF_HB1, OFF_XB,
                  sHB0, sHB1, sXB, sWhB, sWxB, ctrB,
                  bz, cB, lane, wm, wn, srow, tr, tc, q);
    }
}

// ---------------- projection + softmax ---------------------------------------
__global__ void proj_kernel(const float* __restrict__ Wp, const float* __restrict__ bp,
                            float* __restrict__ out) {
    __shared__ float hs[512];
    __shared__ float wred[8];
    int b = blockIdx.x, o = threadIdx.x;
    for (int i = o; i < 512; i += 128)
        hs[i] = fminf(fmaxf(g_hfinal[(size_t)b * 512 + i], -1.f), 1.f);
    __syncthreads();
    float acc = bp[o];
#pragma unroll 8
    for (int k = 0; k < 512; k++) acc = fmaf(hs[k], Wp[(size_t)k * 128 + o], acc);
    float m = acc;
#pragma unroll
    for (int s = 16; s > 0; s >>= 1) m = fmaxf(m, __shfl_xor_sync(0xffffffffu, m, s));
    int w = o >> 5, ln = o & 31;
    if (ln == 0) wred[w] = m;
    __syncthreads();
    m = fmaxf(fmaxf(wred[0], wred[1]), fmaxf(wred[2], wred[3]));
    float e = __expf(acc - m);
    float s = e;
#pragma unroll
    for (int sh = 16; sh > 0; sh >>= 1) s += __shfl_xor_sync(0xffffffffu, s, sh);
    if (ln == 0) wred[4 + w] = s;
    __syncthreads();
    s = wred[4] + wred[5] + wred[6] + wred[7];
    out[(size_t)b * 128 + o] = e * __fdividef(1.f, s);
}

// ---------------- launch ------------------------------------------------------
// Inputs resolved BY ELEMENT COUNT (all six sizes distinct):
//   x: 33554432, Wx: 262144, Wh: 1048576, b: 2048, Wp: 65536, bp: 128
extern "C" void kernel_launch(void* const* d_in, const int* in_sizes, int n_in,
                              void* d_out, int out_size) {
    (void)out_size;
    const float *x = 0, *Wx = 0, *Wh = 0, *b = 0, *Wp = 0, *bp = 0;
    for (int i = 0; i < n_in; i++) {
        switch (in_sizes[i]) {
            case 512 * 512 * 128: x  = (const float*)d_in[i]; break;
            case 128 * 2048:      Wx = (const float*)d_in[i]; break;
            case 512 * 2048:      Wh = (const float*)d_in[i]; break;
            case 2048:            b  = (const float*)d_in[i]; break;
            case 512 * 128:       Wp = (const float*)d_in[i]; break;
            case 128:             bp = (const float*)d_in[i]; break;
            default: break;
        }
    }
    float* out = (float*)d_out;

    cudaFuncSetAttribute(lstm_rec, cudaFuncAttributeMaxDynamicSharedMemorySize, REC_SMEM);

    conv_w<<<512, 256>>>(Wx, Wh);
    conv_x<<<512, 256>>>(x);
    reset_k<<<128, 256>>>();
    lstm_rec<<<NCTA, 256, REC_SMEM>>>(b);
    proj_kernel<<<512, 128>>>(Wp, bp, out);
}

// round 16
// speedup vs baseline: 1.2155x; 1.2155x over previous
#include <cuda_runtime.h>
#include <cuda_bf16.h>
#include <cstdint>
#include <cstddef>

// ---------------------------------------------------------------------------
// LSTM: B=512, T=512, I=128, H=512, O=128. Gates [g,i,f,o].
// Persistent 128 CTAs x 512 threads. TWO independent 64-row tiles per CTA:
// warps 0-7 run tile A, warps 8-15 run tile B (same q -> shared Whs/Wxs).
// Hardware warp interleaving hides each tile's h-exchange latency under the
// other tile's compute. Per-tile loop = round-11's proven structure.
// ---------------------------------------------------------------------------

#define NCTA 128

__device__ __nv_bfloat16  g_wxtb[2048 * 128];            // Wx^T [n][k] bf16
__device__ __nv_bfloat16  g_wht[2048 * 512];             // Wh^T [n][k] bf16
__device__ __nv_bfloat16  g_xb[(size_t)512 * 512 * 128]; // x bf16 [b][t][i]
__device__ __nv_bfloat16  g_h[2][512 * 512];             // ping-pong h
__device__ float          g_hfinal[512 * 512];           // final h fp32
__device__ unsigned       g_barr[8 * 32];                // per-group ctr @ [g*32]

// ---------------- PTX helpers ----------------------------------------------
__device__ __forceinline__ unsigned smem_u32(const void* p) {
    return (unsigned)__cvta_generic_to_shared(p);
}
__device__ __forceinline__ void cp16(void* dst_smem, const void* src) {
    asm volatile("cp.async.cg.shared.global [%0], [%1], 16;"
                 :: "r"(smem_u32(dst_smem)), "l"(src) : "memory");
}
__device__ __forceinline__ void cp_commit() {
    asm volatile("cp.async.commit_group;" ::: "memory");
}
template <int N>
__device__ __forceinline__ void cp_wait() {
    asm volatile("cp.async.wait_group %0;" :: "n"(N) : "memory");
}
__device__ __forceinline__ void ldm4(unsigned r[4], unsigned addr) {
    asm volatile("ldmatrix.sync.aligned.m8n8.x4.shared.b16 {%0,%1,%2,%3}, [%4];"
                 : "=r"(r[0]), "=r"(r[1]), "=r"(r[2]), "=r"(r[3]) : "r"(addr));
}
__device__ __forceinline__ void mma_bf16(float& d0, float& d1, float& d2, float& d3,
                                         unsigned a0, unsigned a1, unsigned a2, unsigned a3,
                                         unsigned b0, unsigned b1) {
    asm volatile(
        "mma.sync.aligned.m16n8k16.row.col.f32.bf16.bf16.f32 "
        "{%0,%1,%2,%3},{%4,%5,%6,%7},{%8,%9},{%0,%1,%2,%3};"
        : "+f"(d0), "+f"(d1), "+f"(d2), "+f"(d3)
        : "r"(a0), "r"(a1), "r"(a2), "r"(a3), "r"(b0), "r"(b1));
}
__device__ __forceinline__ float tanhfast(float x) {
    float y;
    asm("tanh.approx.f32 %0, %1;" : "=f"(y) : "f"(x));
    return y;
}
__device__ __forceinline__ float fsig(float x) {
    return fmaf(0.5f, tanhfast(0.5f * x), 0.5f);
}
// pair bar: warps {wm, wm+4} within a tile group; ids 1..8, 64 threads
__device__ __forceinline__ void barpair(int id) {
    asm volatile("bar.sync %0, 64;" :: "r"(id) : "memory");
}

// ---- mma block: M=16 x (4 gates x n8), 8 k16 iterations (R15-verified) ------
__device__ __forceinline__ void mma_block8(unsigned aAddr, unsigned bAddr,
                                           unsigned gs, float acc[4][4]) {
#pragma unroll
    for (int k16 = 0; k16 < 8; k16++) {
        unsigned a[4], b01[4], b23[4];
        ldm4(a, aAddr + k16 * 32);
        ldm4(b01, bAddr + k16 * 32);
        ldm4(b23, bAddr + gs + k16 * 32);
        mma_bf16(acc[0][0], acc[0][1], acc[0][2], acc[0][3],
                 a[0], a[1], a[2], a[3], b01[0], b01[1]);
        mma_bf16(acc[1][0], acc[1][1], acc[1][2], acc[1][3],
                 a[0], a[1], a[2], a[3], b01[2], b01[3]);
        mma_bf16(acc[2][0], acc[2][1], acc[2][2], acc[2][3],
                 a[0], a[1], a[2], a[3], b23[0], b23[1]);
        mma_bf16(acc[3][0], acc[3][1], acc[3][2], acc[3][3],
                 a[0], a[1], a[2], a[3], b23[2], b23[3]);
    }
}

// ---------------- converts ---------------------------------------------------
__global__ void conv_w(const float* __restrict__ Wx, const float* __restrict__ Wh) {
    int tid = blockIdx.x * blockDim.x + threadIdx.x;
    int stride = gridDim.x * blockDim.x;
    for (int o = tid; o < 2048 * 128; o += stride) {
        int k = o & 127, n = o >> 7;
        g_wxtb[o] = __float2bfloat16(Wx[(size_t)k * 2048 + n]);
    }
    for (int o = tid; o < 2048 * 512; o += stride) {
        int k = o & 511, n = o >> 9;
        g_wht[o] = __float2bfloat16(Wh[(size_t)k * 2048 + n]);
    }
}

__global__ void conv_x(const float* __restrict__ x) {
    const float4* x4 = (const float4*)x;
    size_t N4 = (size_t)512 * 512 * 128 / 4;
    for (size_t o = (size_t)blockIdx.x * blockDim.x + threadIdx.x; o < N4;
         o += (size_t)gridDim.x * blockDim.x) {
        float4 v = x4[o];
        __nv_bfloat162 lo = __floats2bfloat162_rn(v.x, v.y);
        __nv_bfloat162 hi = __floats2bfloat162_rn(v.z, v.w);
        uint2 pk;
        pk.x = *(unsigned*)&lo;
        pk.y = *(unsigned*)&hi;
        *(uint2*)(g_xb + o * 4) = pk;
    }
}

__global__ void reset_k() {
    int tid = blockIdx.x * blockDim.x + threadIdx.x;
    if (tid < 8 * 32) g_barr[tid] = 0u;
    for (int o = tid; o < 512 * 512; o += gridDim.x * blockDim.x)
        g_h[0][o] = __float2bfloat16(0.f);
}

// ---------------- persistent recurrence --------------------------------------
// smem (bytes):
//   Whs [64][520] bf16 : 0      .. 66560
//   Wxs [64][136] bf16 : 66560  .. 83968
//   tile A: buf0 83968, buf1 101376, buf2 118784, xsA 136192
//   tile B: buf0 153600, buf1 171008, buf2 188416, xsB 205824   (end 223232)
#define OFF_WX  66560
#define OFF_TA  83968
#define OFF_TB  153600
#define BUF_B   17408       // one 64x136 bf16 buffer
#define REC_SMEM 223232
__global__ void __launch_bounds__(512, 1) lstm_rec(const float* __restrict__ bias) {
    extern __shared__ char smem[];
    __nv_bfloat16* Whs = (__nv_bfloat16*)smem;
    __nv_bfloat16* Wxs = (__nv_bfloat16*)(smem + OFF_WX);

    const int tid = threadIdx.x;
    const int lane = tid & 31, warp = tid >> 5;
    const int tile = warp >> 3;              // 0 = tile A, 1 = tile B
    const int wl = warp & 7;
    const int wm = wl & 3, wn = wl >> 2;
    const int q = blockIdx.x & 31, gpair = blockIdx.x >> 5;
    const int grpid = 2 * gpair + tile;      // 0..7
    const int rbase = grpid * 64;
    const int tr = lane >> 2, tc = (lane & 3) * 2;
    const int srow = wm * 16 + wn * 8;       // this warp's 8-row staging slice
    const int tbase = tile ? OFF_TB : OFF_TA;
    const int pbid = 1 + tile * 4 + wm;      // pair-bar id
    volatile unsigned* ctr = (volatile unsigned*)&g_barr[grpid << 5];

    // ---- per-thread ldmatrix addresses (R11/R15-verified formulas) ----
    const unsigned aoff =
        (unsigned)(wm * 16 + (lane & 7) + ((lane >> 3) & 1) * 8) * 272u +
        (unsigned)((lane >> 4) & 1) * 16u;
    const unsigned bRow =
        (unsigned)(((lane >> 4) & 1) * 16 + wn * 8 + (lane & 7));
    const unsigned bColSel = (unsigned)((lane >> 3) & 1) * 16u;
    const unsigned sWhB = smem_u32(Whs) + bRow * 1040u + bColSel;   // + kc*256
    const unsigned sWxB = smem_u32(Wxs) + bRow * 272u + bColSel;
    const unsigned base = smem_u32(smem);
    const unsigned sB0 = base + tbase + aoff;
    const unsigned sB1 = sB0 + BUF_B;
    const unsigned sB2 = sB0 + 2 * BUF_B;
    const unsigned sX  = sB0 + 3 * BUF_B;
    char* tb = smem + tbase;
    const unsigned GS_WH = 32u * 1040u;
    const unsigned GS_WX = 32u * 272u;

    // ---- prologue (CTA-wide) ----
    for (int i = tid; i < 4096; i += 512) {          // Whs: 64 rows x 64 ch
        int rowi = i >> 6, ch = i & 63;
        int gate = rowi >> 4, lc = rowi & 15;
        cp16(&Whs[rowi * 520 + ch * 8],
             g_wht + (size_t)(gate * 512 + q * 16 + lc) * 512 + ch * 8);
    }
    for (int i = tid; i < 1024; i += 512) {          // Wxs: 64 rows x 16 ch
        int rowi = i >> 4, ch = i & 15;
        int gate = rowi >> 4, lc = rowi & 15;
        cp16(&Wxs[rowi * 136 + ch * 8],
             g_wxtb + (size_t)(gate * 512 + q * 16 + lc) * 128 + ch * 8);
    }
    for (int i = tid; i < 2048; i += 512) {          // xsA(0) / xsB(0)
        int t2 = i >> 10;                            // 0 -> A, 1 -> B
        int r = (i >> 4) & 63, ch = i & 15;
        cp16(smem + (t2 ? OFF_TB : OFF_TA) + 3 * BUF_B + r * 272 + ch * 16,
             g_xb + ((size_t)((2 * gpair + t2) * 64 + r) * 512 + 0) * 128 + ch * 8);
    }
    cp_commit(); cp_wait<0>(); __syncthreads();

    float bz[4][2];
    {
        int col = q * 16 + wn * 8 + tc;
#pragma unroll
        for (int g = 0; g < 4; g++) {
            bz[g][0] = bias[g * 512 + col];
            bz[g][1] = bias[g * 512 + col + 1];
        }
    }
    float c[4];
#pragma unroll
    for (int e = 0; e < 4; e++) c[e] = 0.f;

    // acc for step 0: bias + x(0)@Wx
    float acc[4][4];
#pragma unroll
    for (int g = 0; g < 4; g++) {
        acc[g][0] = bz[g][0]; acc[g][1] = bz[g][1];
        acc[g][2] = bz[g][0]; acc[g][3] = bz[g][1];
    }
    mma_block8(sX, sWxB, GS_WX, acc);
    __syncthreads();   // last CTA-wide sync; steady loop is warp/pair-local

    for (int t = 0; t < 512; ++t) {
        const __nv_bfloat16* hsrc = g_h[t & 1] + (size_t)rbase * 512;

        // stage this warp's 8-row slice of h chunks 0,1 (two groups)
#pragma unroll
        for (int cc = 0; cc < 2; cc++) {
#pragma unroll
            for (int i = 0; i < 4; i++) {
                int idx = lane + i * 32;
                int r = srow + (idx >> 4), ch = idx & 15;
                cp16(tb + cc * BUF_B + r * 272 + ch * 16,
                     hsrc + (size_t)r * 512 + cc * 128 + ch * 8);
            }
            cp_commit();
        }
        // pending {h0,h1}

        // kc=0: h0 ready; stage h2 -> buf2
        cp_wait<1>(); barpair(pbid);
#pragma unroll
        for (int i = 0; i < 4; i++) {
            int idx = lane + i * 32;
            int r = srow + (idx >> 4), ch = idx & 15;
            cp16(tb + 2 * BUF_B + r * 272 + ch * 16,
                 hsrc + (size_t)r * 512 + 2 * 128 + ch * 8);
        }
        cp_commit();   // {h1,h2}
        mma_block8(sB0, sWhB, GS_WH, acc);

        // kc=1: h1 ready; stage h3 -> buf0
        cp_wait<1>(); barpair(pbid);
#pragma unroll
        for (int i = 0; i < 4; i++) {
            int idx = lane + i * 32;
            int r = srow + (idx >> 4), ch = idx & 15;
            cp16(tb + r * 272 + ch * 16,
                 hsrc + (size_t)r * 512 + 3 * 128 + ch * 8);
        }
        cp_commit();   // {h2,h3}
        mma_block8(sB1, sWhB + 256, GS_WH, acc);

        // kc=2: h2 ready; prefetch x(t+1) slice
        cp_wait<1>(); barpair(pbid);
        if (t < 511) {
#pragma unroll
            for (int i = 0; i < 4; i++) {
                int idx = lane + i * 32;
                int r = srow + (idx >> 4), ch = idx & 15;
                cp16(tb + 3 * BUF_B + r * 272 + ch * 16,
                     g_xb + ((size_t)(rbase + r) * 512 + (t + 1)) * 128 + ch * 8);
            }
            cp_commit();   // {h3,x'}
        }
        mma_block8(sB2, sWhB + 512, GS_WH, acc);

        // kc=3: h3 ready
        if (t < 511) cp_wait<1>(); else cp_wait<0>();
        barpair(pbid);
        mma_block8(sB0, sWhB + 768, GS_WH, acc);

        // ---- gates + state update + h writeback ----
        {
            const int grow = rbase + wm * 16 + tr;
            const int hcol = q * 16 + wn * 8 + tc;
            float hv[4];
#pragma unroll
            for (int e = 0; e < 4; e++) {
                float gv = tanhfast(acc[0][e]);
                float iv = fsig(acc[1][e]);
                float fv = fsig(acc[2][e]);
                float ov = fsig(acc[3][e]);
                float cn = gv * iv + c[e] * fv;
                c[e] = cn;
                hv[e] = tanhfast(cn) * ov;
            }
            if (t < 511) {
                __nv_bfloat16* hd = g_h[(t + 1) & 1];
                *(__nv_bfloat162*)(hd + (size_t)grow * 512 + hcol) =
                    __floats2bfloat162_rn(hv[0], hv[1]);
                *(__nv_bfloat162*)(hd + (size_t)(grow + 8) * 512 + hcol) =
                    __floats2bfloat162_rn(hv[2], hv[3]);
            } else {
                *(float2*)(g_hfinal + (size_t)grow * 512 + hcol) = make_float2(hv[0], hv[1]);
                *(float2*)(g_hfinal + (size_t)(grow + 8) * 512 + hcol) = make_float2(hv[2], hv[3]);
            }
        }

        if (t == 511) break;

        // ---- arrive at this tile's group counter (8 warps x 32 CTAs = 256) ----
        __syncwarp();
        if (lane == 0) {
            __threadfence();
            atomicAdd((unsigned*)ctr, 1u);
        }

        // ---- barrier shadow: x-GEMM for t+1 ----
        cp_wait<0>();      // x' slice complete
        barpair(pbid);     // sibling's x' slice visible too
#pragma unroll
        for (int g = 0; g < 4; g++) {
            acc[g][0] = bz[g][0]; acc[g][1] = bz[g][1];
            acc[g][2] = bz[g][0]; acc[g][3] = bz[g][1];
        }
        mma_block8(sX, sWxB, GS_WX, acc);

        // ---- poll (all lanes; coalesces to one request per warp) ----
        {
            unsigned target = (unsigned)(t + 1) * 256u;
            while (*ctr < target) { }
            __threadfence();
        }
    }
}

// ---------------- projection + softmax ---------------------------------------
__global__ void proj_kernel(const float* __restrict__ Wp, const float* __restrict__ bp,
                            float* __restrict__ out) {
    __shared__ float hs[512];
    __shared__ float wred[8];
    int b = blockIdx.x, o = threadIdx.x;
    for (int i = o; i < 512; i += 128)
        hs[i] = fminf(fmaxf(g_hfinal[(size_t)b * 512 + i], -1.f), 1.f);
    __syncthreads();
    float acc = bp[o];
#pragma unroll 8
    for (int k = 0; k < 512; k++) acc = fmaf(hs[k], Wp[(size_t)k * 128 + o], acc);
    float m = acc;
#pragma unroll
    for (int s = 16; s > 0; s >>= 1) m = fmaxf(m, __shfl_xor_sync(0xffffffffu, m, s));
    int w = o >> 5, ln = o & 31;
    if (ln == 0) wred[w] = m;
    __syncthreads();
    m = fmaxf(fmaxf(wred[0], wred[1]), fmaxf(wred[2], wred[3]));
    float e = __expf(acc - m);
    float s = e;
#pragma unroll
    for (int sh = 16; sh > 0; sh >>= 1) s += __shfl_xor_sync(0xffffffffu, s, sh);
    if (ln == 0) wred[4 + w] = s;
    __syncthreads();
    s = wred[4] + wred[5] + wred[6] + wred[7];
    out[(size_t)b * 128 + o] = e * __fdividef(1.f, s);
}

// ---------------- launch ------------------------------------------------------
// Inputs resolved BY ELEMENT COUNT (all six sizes distinct):
//   x: 33554432, Wx: 262144, Wh: 1048576, b: 2048, Wp: 65536, bp: 128
extern "C" void kernel_launch(void* const* d_in, const int* in_sizes, int n_in,
                              void* d_out, int out_size) {
    (void)out_size;
    const float *x = 0, *Wx = 0, *Wh = 0, *b = 0, *Wp = 0, *bp = 0;
    for (int i = 0; i < n_in; i++) {
        switch (in_sizes[i]) {
            case 512 * 512 * 128: x  = (const float*)d_in[i]; break;
            case 128 * 2048:      Wx = (const float*)d_in[i]; break;
            case 512 * 2048:      Wh = (const float*)d_in[i]; break;
            case 2048:            b  = (const float*)d_in[i]; break;
            case 512 * 128:       Wp = (const float*)d_in[i]; break;
            case 128:             bp = (const float*)d_in[i]; break;
            default: break;
        }
    }
    float* out = (float*)d_out;

    cudaFuncSetAttribute(lstm_rec, cudaFuncAttributeMaxDynamicSharedMemorySize, REC_SMEM);

    conv_w<<<512, 256>>>(Wx, Wh);
    conv_x<<<512, 256>>>(x);
    reset_k<<<128, 256>>>();
    lstm_rec<<<NCTA, 512, REC_SMEM>>>(b);
    proj_kernel<<<512, 128>>>(Wp, bp, out);
}

// round 17
// speedup vs baseline: 1.3220x; 1.0876x over previous
#include <cuda_runtime.h>
#include <cuda_bf16.h>
#include <cstdint>
#include <cstddef>

// ---------------------------------------------------------------------------
// LSTM: B=512, T=512, I=128, H=512, O=128. Gates [g,i,f,o].
// Persistent 128 CTAs. CTA (p,q): p = 128-row batch tile (4 groups),
// q = 16 h-cols x 4 gates = 64 N cols. Weights smem-resident.
// Round-17 = round-11 (best, 3421us) + release/acquire atomics (no MEMBAR.GPU
// in the hot loop) + nanosleep-backoff polling (counter-line decongestion).
// ---------------------------------------------------------------------------

#define NCTA 128

__device__ __nv_bfloat16  g_wxtb[2048 * 128];            // Wx^T [n][k] bf16
__device__ __nv_bfloat16  g_wht[2048 * 512];             // Wh^T [n][k] bf16
__device__ __nv_bfloat16  g_xb[(size_t)512 * 512 * 128]; // x bf16 [b][t][i]
__device__ __nv_bfloat16  g_h[2][512 * 512];             // ping-pong h
__device__ float          g_hfinal[512 * 512];           // final h fp32
__device__ unsigned       g_barr[32 * 32];               // per-p counters @ [p*32]

// ---------------- PTX helpers ----------------------------------------------
__device__ __forceinline__ unsigned smem_u32(const void* p) {
    return (unsigned)__cvta_generic_to_shared(p);
}
__device__ __forceinline__ void cp16(void* dst_smem, const void* src) {
    asm volatile("cp.async.cg.shared.global [%0], [%1], 16;"
                 :: "r"(smem_u32(dst_smem)), "l"(src) : "memory");
}
__device__ __forceinline__ void cp_commit() {
    asm volatile("cp.async.commit_group;" ::: "memory");
}
template <int N>
__device__ __forceinline__ void cp_wait() {
    asm volatile("cp.async.wait_group %0;" :: "n"(N) : "memory");
}
__device__ __forceinline__ void ldm4(unsigned r[4], unsigned addr) {
    asm volatile("ldmatrix.sync.aligned.m8n8.x4.shared.b16 {%0,%1,%2,%3}, [%4];"
                 : "=r"(r[0]), "=r"(r[1]), "=r"(r[2]), "=r"(r[3]) : "r"(addr));
}
__device__ __forceinline__ void mma_bf16(float& d0, float& d1, float& d2, float& d3,
                                         unsigned a0, unsigned a1, unsigned a2, unsigned a3,
                                         unsigned b0, unsigned b1) {
    asm volatile(
        "mma.sync.aligned.m16n8k16.row.col.f32.bf16.bf16.f32 "
        "{%0,%1,%2,%3},{%4,%5,%6,%7},{%8,%9},{%0,%1,%2,%3};"
        : "+f"(d0), "+f"(d1), "+f"(d2), "+f"(d3)
        : "r"(a0), "r"(a1), "r"(a2), "r"(a3), "r"(b0), "r"(b1));
}
__device__ __forceinline__ float tanhfast(float x) {
    float y;
    asm("tanh.approx.f32 %0, %1;" : "=f"(y) : "f"(x));
    return y;
}
__device__ __forceinline__ float fsig(float x) {
    return fmaf(0.5f, tanhfast(0.5f * x), 0.5f);
}
// pair-local named barrier: warps (wm,0) and (wm,1), 64 threads, id = wm+1
__device__ __forceinline__ void barpair(int wm) {
    asm volatile("bar.sync %0, 64;" :: "r"(wm + 1) : "memory");
}
// release arrival: orders all prior stores (h writeback) before the increment
__device__ __forceinline__ void arrive_release(unsigned* ctr) {
    asm volatile("red.release.gpu.global.add.u32 [%0], 1;" :: "l"(ctr) : "memory");
}
// acquire poll load: orders subsequent loads after the observed counter value
__device__ __forceinline__ unsigned ld_acquire(const unsigned* ctr) {
    unsigned v;
    asm volatile("ld.acquire.gpu.global.u32 %0, [%1];" : "=r"(v) : "l"(ctr) : "memory");
    return v;
}

// ---- mma block: 8 k16 iterations via ldmatrix (layout proven round 10) ----
__device__ __forceinline__ void mma_block8(unsigned aAddr, unsigned bAddr,
                                           unsigned bPairStride, float acc[2][4][4]) {
#pragma unroll
    for (int k16 = 0; k16 < 8; k16++) {
        unsigned a[2][4], b01[4], b23[4];
        ldm4(a[0], aAddr + k16 * 32);
        ldm4(a[1], aAddr + 4352 + k16 * 32);
        ldm4(b01, bAddr + k16 * 32);
        ldm4(b23, bAddr + bPairStride + k16 * 32);
#pragma unroll
        for (int im = 0; im < 2; im++) {
            mma_bf16(acc[im][0][0], acc[im][0][1], acc[im][0][2], acc[im][0][3],
                     a[im][0], a[im][1], a[im][2], a[im][3], b01[0], b01[1]);
            mma_bf16(acc[im][1][0], acc[im][1][1], acc[im][1][2], acc[im][1][3],
                     a[im][0], a[im][1], a[im][2], a[im][3], b01[2], b01[3]);
            mma_bf16(acc[im][2][0], acc[im][2][1], acc[im][2][2], acc[im][2][3],
                     a[im][0], a[im][1], a[im][2], a[im][3], b23[0], b23[1]);
            mma_bf16(acc[im][3][0], acc[im][3][1], acc[im][3][2], acc[im][3][3],
                     a[im][0], a[im][1], a[im][2], a[im][3], b23[2], b23[3]);
        }
    }
}

// ---------------- converts ---------------------------------------------------
__global__ void conv_w(const float* __restrict__ Wx, const float* __restrict__ Wh) {
    int tid = blockIdx.x * blockDim.x + threadIdx.x;
    int stride = gridDim.x * blockDim.x;
    for (int o = tid; o < 2048 * 128; o += stride) {
        int k = o & 127, n = o >> 7;
        g_wxtb[o] = __float2bfloat16(Wx[(size_t)k * 2048 + n]);
    }
    for (int o = tid; o < 2048 * 512; o += stride) {
        int k = o & 511, n = o >> 9;
        g_wht[o] = __float2bfloat16(Wh[(size_t)k * 2048 + n]);
    }
}

__global__ void conv_x(const float* __restrict__ x) {
    const float4* x4 = (const float4*)x;
    size_t N4 = (size_t)512 * 512 * 128 / 4;
    for (size_t o = (size_t)blockIdx.x * blockDim.x + threadIdx.x; o < N4;
         o += (size_t)gridDim.x * blockDim.x) {
        float4 v = x4[o];
        __nv_bfloat162 lo = __floats2bfloat162_rn(v.x, v.y);
        __nv_bfloat162 hi = __floats2bfloat162_rn(v.z, v.w);
        uint2 pk;
        pk.x = *(unsigned*)&lo;
        pk.y = *(unsigned*)&hi;
        *(uint2*)(g_xb + o * 4) = pk;
    }
}

__global__ void reset_k() {
    int tid = blockIdx.x * blockDim.x + threadIdx.x;
    if (tid < 32 * 32) g_barr[tid] = 0u;
    for (int o = tid; o < 512 * 512; o += gridDim.x * blockDim.x)
        g_h[0][o] = __float2bfloat16(0.f);
}

// ---------------- persistent recurrence --------------------------------------
// smem layout (bytes):
//   Whs [64][520] bf16 : 0      .. 66560
//   Wxs [64][136] bf16 : 66560  .. 83968
//   As  3x[128][136] bf16 : 83968 .. 188416   (3 x 34816)
//   xs  [128][136] bf16 : 188416 .. 223232
#define AS_ELEMS (128 * 136)
#define AS_BYTES 34816
#define REC_SMEM 223232
__global__ void __launch_bounds__(256, 1) lstm_rec(const float* __restrict__ bias) {
    extern __shared__ char smem[];
    __nv_bfloat16* Whs = (__nv_bfloat16*)smem;
    __nv_bfloat16* Wxs = (__nv_bfloat16*)(smem + 66560);
    __nv_bfloat16* As0 = (__nv_bfloat16*)(smem + 83968);
    __nv_bfloat16* xs  = (__nv_bfloat16*)(smem + 188416);

    const int tid = threadIdx.x;
    const int lane = tid & 31, warp = tid >> 5;
    const int wm = warp & 3, wn = warp >> 2;
    const int q = blockIdx.x & 31, p = blockIdx.x >> 5;
    const int tr = lane >> 2, tc = (lane & 3) * 2;
    const int rbase = p * 128;
    const int pairrow = wm * 32 + wn * 16;   // this warp's 16-row staging slice
    unsigned* barp = &g_barr[p << 5];

    // ---- per-thread ldmatrix addresses (verified in round 10) ----
    const unsigned aoff =
        (unsigned)(wm * 32 + (lane & 7) + ((lane >> 3) & 1) * 8) * 272u +
        (unsigned)((lane >> 4) & 1) * 16u;
    const unsigned bRowWh =
        (unsigned)(((lane >> 4) & 1) * 16 + wn * 8 + (lane & 7));
    const unsigned bColSel = (unsigned)((lane >> 3) & 1) * 16u;
    const unsigned sWh = smem_u32(Whs) + bRowWh * 1040u + bColSel;   // + kc*256
    const unsigned sWx = smem_u32(Wxs) + bRowWh * 272u + bColSel;
    const unsigned sX  = smem_u32(xs) + aoff;
    unsigned sA[3];
    sA[0] = smem_u32(As0) + aoff;
    sA[1] = sA[0] + AS_BYTES;
    sA[2] = sA[0] + 2 * AS_BYTES;
    const unsigned WH_PAIR = 32u * 1040u;
    const unsigned WX_PAIR = 32u * 272u;

    // ---- prologue (CTA-wide, syncthreads allowed here) ----
    for (int i = tid; i < 4096; i += 256) {
        int rowi = i >> 6, ch = i & 63;
        int gate = rowi >> 4, lc = rowi & 15;
        cp16(&Whs[rowi * 520 + ch * 8],
             g_wht + (size_t)(gate * 512 + q * 16 + lc) * 512 + ch * 8);
    }
    for (int i = tid; i < 1024; i += 256) {
        int rowi = i >> 4, ch = i & 15;
        int gate = rowi >> 4, lc = rowi & 15;
        cp16(&Wxs[rowi * 136 + ch * 8],
             g_wxtb + (size_t)(gate * 512 + q * 16 + lc) * 128 + ch * 8);
    }
    for (int i = tid; i < 2048; i += 256) {
        int r = i >> 4, ch = i & 15;
        cp16(&xs[r * 136 + ch * 8],
             g_xb + ((size_t)(rbase + r) * 512 + 0) * 128 + ch * 8);
    }
    cp_commit(); cp_wait<0>(); __syncthreads();

    float bz[4][2];
    {
        int col = q * 16 + wn * 8 + tc;
#pragma unroll
        for (int g = 0; g < 4; g++) {
            bz[g][0] = bias[g * 512 + col];
            bz[g][1] = bias[g * 512 + col + 1];
        }
    }

    float c[2][4];
#pragma unroll
    for (int im = 0; im < 2; im++)
#pragma unroll
        for (int e = 0; e < 4; e++) c[im][e] = 0.f;

    // acc for step 0: bias + x(0)@Wx
    float acc[2][4][4];
#pragma unroll
    for (int im = 0; im < 2; im++)
#pragma unroll
        for (int g = 0; g < 4; g++) {
            acc[im][g][0] = bz[g][0]; acc[im][g][1] = bz[g][1];
            acc[im][g][2] = bz[g][0]; acc[im][g][3] = bz[g][1];
        }
    mma_block8(sX, sWx, WX_PAIR, acc);
    __syncthreads();   // last CTA-wide sync; steady loop is warp/pair-local

    for (int t = 0; t < 512; ++t) {
        const int cur = t & 1, nxt = cur ^ 1;
        const __nv_bfloat16* hsrc = g_h[cur] + (size_t)(rbase + pairrow) * 512;

        // stage this warp's 16-row slice of h chunks 0,1 (two groups)
#pragma unroll
        for (int cc = 0; cc < 2; cc++) {
            __nv_bfloat16* buf = As0 + cc * AS_ELEMS;
            for (int i = lane; i < 256; i += 32) {
                int r = i >> 4, ch = i & 15;
                cp16(buf + (pairrow + r) * 136 + ch * 8,
                     hsrc + (size_t)r * 512 + cc * 128 + ch * 8);
            }
            cp_commit();
        }
        // pending {h0,h1}

        // kc=0: h0 ready; stage h2 -> buf2
        cp_wait<1>(); barpair(wm);
        for (int i = lane; i < 256; i += 32) {
            int r = i >> 4, ch = i & 15;
            cp16(As0 + 2 * AS_ELEMS + (pairrow + r) * 136 + ch * 8,
                 hsrc + (size_t)r * 512 + 2 * 128 + ch * 8);
        }
        cp_commit();   // {h1,h2}
        mma_block8(sA[0], sWh, WH_PAIR, acc);

        // kc=1: h1 ready; stage h3 -> buf0 (pair done with buf0 via barpair)
        cp_wait<1>(); barpair(wm);
        for (int i = lane; i < 256; i += 32) {
            int r = i >> 4, ch = i & 15;
            cp16(As0 + (pairrow + r) * 136 + ch * 8,
                 hsrc + (size_t)r * 512 + 3 * 128 + ch * 8);
        }
        cp_commit();   // {h2,h3}
        mma_block8(sA[1], sWh + 256, WH_PAIR, acc);

        // kc=2: h2 ready; prefetch x(t+1) slice
        cp_wait<1>(); barpair(wm);
        if (t < 511) {
            for (int i = lane; i < 256; i += 32) {
                int r = i >> 4, ch = i & 15;
                cp16(xs + (pairrow + r) * 136 + ch * 8,
                     g_xb + ((size_t)(rbase + pairrow + r) * 512 + (t + 1)) * 128 + ch * 8);
            }
            cp_commit();   // {h3,x'}
        }
        mma_block8(sA[2], sWh + 512, WH_PAIR, acc);

        // kc=3: h3 ready
        if (t < 511) cp_wait<1>(); else cp_wait<0>();
        barpair(wm);
        mma_block8(sA[0], sWh + 768, WH_PAIR, acc);

        // ---- gates + state update + h writeback (MUFU.TANH) ----
#pragma unroll
        for (int im = 0; im < 2; im++) {
            int grow = rbase + wm * 32 + im * 16 + tr;
            int hcol = q * 16 + wn * 8 + tc;
            float hv[4];
#pragma unroll
            for (int e = 0; e < 4; e++) {
                float gv = tanhfast(acc[im][0][e]);
                float iv = fsig(acc[im][1][e]);
                float fv = fsig(acc[im][2][e]);
                float ov = fsig(acc[im][3][e]);
                float cc2 = gv * iv + c[im][e] * fv;
                c[im][e] = cc2;
                hv[e] = tanhfast(cc2) * ov;
            }
            if (t < 511) {
                *(__nv_bfloat162*)(g_h[nxt] + (size_t)grow * 512 + hcol) =
                    __floats2bfloat162_rn(hv[0], hv[1]);
                *(__nv_bfloat162*)(g_h[nxt] + (size_t)(grow + 8) * 512 + hcol) =
                    __floats2bfloat162_rn(hv[2], hv[3]);
            } else {
                *(float2*)(g_hfinal + (size_t)grow * 512 + hcol) = make_float2(hv[0], hv[1]);
                *(float2*)(g_hfinal + (size_t)(grow + 8) * 512 + hcol) = make_float2(hv[2], hv[3]);
            }
        }

        if (t == 511) break;

        // ---- warp-granular arrival: release-red (no MEMBAR, no return trip) ----
        __syncwarp();
        if (lane == 0) arrive_release(barp);

        // ---- barrier shadow: x-GEMM for t+1 ----
        cp_wait<0>();      // x' slice complete (this thread's FIFO drained)
        barpair(wm);       // sibling's x' slice visible too
#pragma unroll
        for (int im = 0; im < 2; im++)
#pragma unroll
            for (int g = 0; g < 4; g++) {
                acc[im][g][0] = bz[g][0]; acc[im][g][1] = bz[g][1];
                acc[im][g][2] = bz[g][0]; acc[im][g][3] = bz[g][1];
            }
        mma_block8(sX, sWx, WX_PAIR, acc);

        // ---- poll: acquire load, tight first check then nanosleep backoff ----
        {
            unsigned target = (unsigned)(t + 1) * 256u;
            if (ld_acquire(barp) < target) {
                do { __nanosleep(50); } while (ld_acquire(barp) < target);
            }
        }
    }
}

// ---------------- projection + softmax ---------------------------------------
__global__ void proj_kernel(const float* __restrict__ Wp, const float* __restrict__ bp,
                            float* __restrict__ out) {
    __shared__ float hs[512];
    __shared__ float wred[8];
    int b = blockIdx.x, o = threadIdx.x;
    for (int i = o; i < 512; i += 128)
        hs[i] = fminf(fmaxf(g_hfinal[(size_t)b * 512 + i], -1.f), 1.f);
    __syncthreads();
    float acc = bp[o];
#pragma unroll 8
    for (int k = 0; k < 512; k++) acc = fmaf(hs[k], Wp[(size_t)k * 128 + o], acc);
    float m = acc;
#pragma unroll
    for (int s = 16; s > 0; s >>= 1) m = fmaxf(m, __shfl_xor_sync(0xffffffffu, m, s));
    int w = o >> 5, ln = o & 31;
    if (ln == 0) wred[w] = m;
    __syncthreads();
    m = fmaxf(fmaxf(wred[0], wred[1]), fmaxf(wred[2], wred[3]));
    float e = __expf(acc - m);
    float s = e;
#pragma unroll
    for (int sh = 16; sh > 0; sh >>= 1) s += __shfl_xor_sync(0xffffffffu, s, sh);
    if (ln == 0) wred[4 + w] = s;
    __syncthreads();
    s = wred[4] + wred[5] + wred[6] + wred[7];
    out[(size_t)b * 128 + o] = e * __fdividef(1.f, s);
}

// ---------------- launch ------------------------------------------------------
// Inputs resolved BY ELEMENT COUNT (all six sizes distinct):
//   x: 33554432, Wx: 262144, Wh: 1048576, b: 2048, Wp: 65536, bp: 128
extern "C" void kernel_launch(void* const* d_in, const int* in_sizes, int n_in,
                              void* d_out, int out_size) {
    (void)out_size;
    const float *x = 0, *Wx = 0, *Wh = 0, *b = 0, *Wp = 0, *bp = 0;
    for (int i = 0; i < n_in; i++) {
        switch (in_sizes[i]) {
            case 512 * 512 * 128: x  = (const float*)d_in[i]; break;
            case 128 * 2048:      Wx = (const float*)d_in[i]; break;
            case 512 * 2048:      Wh = (const float*)d_in[i]; break;
            case 2048:            b  = (const float*)d_in[i]; break;
            case 512 * 128:       Wp = (const float*)d_in[i]; break;
            case 128:             bp = (const float*)d_in[i]; break;
            default: break;
        }
    }
    float* out = (float*)d_out;

    cudaFuncSetAttribute(lstm_rec, cudaFuncAttributeMaxDynamicSharedMemorySize, REC_SMEM);

    conv_w<<<512, 256>>>(Wx, Wh);
    conv_x<<<512, 256>>>(x);
    reset_k<<<128, 256>>>();
    lstm_rec<<<NCTA, 256, REC_SMEM>>>(b);
    proj_kernel<<<512, 128>>>(Wp, bp, out);
}